// round 5
// baseline (speedup 1.0000x reference)
#include <cuda_runtime.h>
#include <cuda_bf16.h>

#define BATCH 4
#define NPTS  16384
#define MCTR  4096
#define KNB   32
#define R2    0.01f
#define RMARG 0.1005f
#define RM2   (RMARG * RMARG)
#define CH    6
#define NCELL 1000          // 10x10x10 per batch
#define TCELL 4096
#define CAP   128
#define PPT   16            // points per thread in build (16384/1024)

// Scratch (__device__ globals: allocation-guard-safe)
__device__ float4 g_pts4 [BATCH * NPTS];     // orig order (x,y,z,p2)
__device__ float4 g_spts4[BATCH * NPTS];     // cell-sorted (x,y,z,bitcast idx)
__device__ int    g_off  [TCELL + 1];
__device__ int    g_idx  [BATCH * MCTR * KNB];

// ---------------------------------------------------------------------------
// Fused build: one block per batch. count -> scan -> scatter, all in-block.
// ---------------------------------------------------------------------------
__global__ __launch_bounds__(1024) void build_kernel(const float* __restrict__ pts) {
    __shared__ int scnt[NCELL];     // counts, then reused as per-cell offsets
    __shared__ int s[1024];

    int b   = blockIdx.x;
    int tid = threadIdx.x;
    const float* __restrict__ px = pts + (size_t)b * 3 * NPTS;

    for (int i = tid; i < NCELL; i += 1024) scnt[i] = 0;
    __syncthreads();

    // Phase A: count + remember (rank, cell) per point
    int packed[PPT];
    #pragma unroll
    for (int i = 0; i < PPT; i++) {
        int n = tid + i * 1024;
        float x = px[n], y = px[NPTS + n], z = px[2 * NPTS + n];
        int ci = min(9, max(0, (int)(x * 10.0f)));
        int cj = min(9, max(0, (int)(y * 10.0f)));
        int ck = min(9, max(0, (int)(z * 10.0f)));
        int cell = (ci * 10 + cj) * 10 + ck;
        int rank = atomicAdd(&scnt[cell], 1);
        packed[i] = (rank << 10) | cell;
    }
    __syncthreads();

    // Phase B: exclusive scan over 1024 slots (cells >= NCELL contribute 0)
    int v = (tid < NCELL) ? scnt[tid] : 0;
    s[tid] = v;
    __syncthreads();
    #pragma unroll
    for (int off = 1; off < 1024; off <<= 1) {
        int t = (tid >= off) ? s[tid - off] : 0;
        __syncthreads();
        s[tid] += t;
        __syncthreads();
    }
    int excl = s[tid] - v;
    if (tid < NCELL) {
        scnt[tid] = excl;                           // reuse as local offset
        g_off[b * NCELL + tid] = b * NPTS + excl;
    }
    if (tid == 0)
        g_off[b * NCELL + NCELL] = (b + 1) * NPTS;  // batch boundary sentinel
    __syncthreads();

    // Phase C: scatter (reload coords — L1/L2 hot), write both layouts
    #pragma unroll
    for (int i = 0; i < PPT; i++) {
        int n = tid + i * 1024;
        float x = px[n], y = px[NPTS + n], z = px[2 * NPTS + n];
        float p2 = __fmaf_rn(z, z, __fmaf_rn(y, y, __fmul_rn(x, x)));
        g_pts4[(size_t)b * NPTS + n] = make_float4(x, y, z, p2);
        int cell = packed[i] & 1023;
        int rank = packed[i] >> 10;
        int pos  = b * NPTS + scnt[cell] + rank;
        g_spts4[pos] = make_float4(x, y, z, __int_as_float(n));
    }
}

// ---------------------------------------------------------------------------
// warp-per-center query: merged z-spans, xy-column prune, register bitonic sort
// ---------------------------------------------------------------------------
__global__ __launch_bounds__(256) void query_kernel(const float* __restrict__ centers) {
    __shared__ int lists[8][CAP];
    int gw   = (blockIdx.x * blockDim.x + threadIdx.x) >> 5;
    int wslt = threadIdx.x >> 5;
    int lane = threadIdx.x & 31;
    int b = gw / MCTR, m = gw - b * MCTR;

    const float* c = centers + (size_t)b * 3 * MCTR;
    float cx = c[m], cy = c[MCTR + m], cz = c[2 * MCTR + m];
    float c2 = __fmaf_rn(cz, cz, __fmaf_rn(cy, cy, __fmul_rn(cx, cx)));

    int i0 = max(0, (int)((cx - RMARG) * 10.0f)), i1 = min(9, (int)((cx + RMARG) * 10.0f));
    int j0 = max(0, (int)((cy - RMARG) * 10.0f)), j1 = min(9, (int)((cy + RMARG) * 10.0f));
    int k0 = max(0, (int)((cz - RMARG) * 10.0f)), k1 = min(9, (int)((cz + RMARG) * 10.0f));

    int* lst = lists[wslt];
    unsigned below = (1u << lane) - 1u;
    unsigned cnt = 0;

    for (int ci = i0; ci <= i1; ci++) {
        float lox = ci * 0.1f, hix = lox + 0.1f;
        float dxm = fmaxf(fmaxf(lox - cx, cx - hix), 0.0f);
        float dx2 = dxm * dxm;
        for (int cj = j0; cj <= j1; cj++) {
            float loy = cj * 0.1f, hiy = loy + 0.1f;
            float dym = fmaxf(fmaxf(loy - cy, cy - hiy), 0.0f);
            if (__fmaf_rn(dym, dym, dx2) >= RM2) continue;   // column prune

            int cb = b * NCELL + (ci * 10 + cj) * 10;        // z-cells contiguous
            int start = g_off[cb + k0];
            int end   = g_off[cb + k1 + 1];
            for (int pb = start; pb < end; pb += 32) {
                int p = pb + lane;
                bool hit = false; int idxv = 0;
                if (p < end) {
                    float4 q = g_spts4[p];
                    float p2 = __fmaf_rn(q.z, q.z, __fmaf_rn(q.y, q.y, __fmul_rn(q.x, q.x)));
                    float cp = __fmaf_rn(cz, q.z, __fmaf_rn(cy, q.y, __fmul_rn(cx, q.x)));
                    float d2 = __fsub_rn(__fadd_rn(c2, p2), __fmul_rn(2.0f, cp));
                    hit = d2 < R2;
                    idxv = __float_as_int(q.w);
                }
                unsigned msk = __ballot_sync(0xffffffffu, hit);
                unsigned pos = cnt + __popc(msk & below);
                if (hit && pos < CAP) lst[pos] = idxv;
                cnt += __popc(msk);
            }
        }
    }

    int eff = min((int)cnt, CAP);
    for (int t = eff + lane; t < CAP; t += 32) lst[t] = 0x7fffffff;
    __syncwarp();

    // register bitonic sort of 128 (4 regs/lane, i = q*32 + lane)
    int r[4];
    #pragma unroll
    for (int q = 0; q < 4; q++) r[q] = lst[q * 32 + lane];

    #pragma unroll
    for (int k2 = 2; k2 <= CAP; k2 <<= 1) {
        #pragma unroll
        for (int j = CAP / 2; j > 0; j >>= 1) {
            if (j >= k2) continue;
            if (j >= 32) {
                int jq = j >> 5;
                #pragma unroll
                for (int q = 0; q < 4; q++) {
                    int qp = q ^ jq;
                    if (qp > q) {
                        bool up = (((q * 32 + lane) & k2) == 0);
                        int a = r[q], bb = r[qp];
                        if ((a > bb) == up) { r[q] = bb; r[qp] = a; }
                    }
                }
            } else {
                #pragma unroll
                for (int q = 0; q < 4; q++) {
                    int i = q * 32 + lane;
                    bool up = ((i & k2) == 0);
                    int part = __shfl_xor_sync(0xffffffffu, r[q], j);
                    bool takeMin = (((lane & j) == 0) == up);
                    r[q] = takeMin ? min(r[q], part) : max(r[q], part);
                }
            }
        }
    }

    g_idx[(size_t)gw * KNB + lane] = (lane < eff) ? r[0] : 0;
}

// ---------------------------------------------------------------------------
// tiled gather: 32 centers/block, MLP-4 random loads, coalesced writes along m
// ---------------------------------------------------------------------------
__global__ __launch_bounds__(256) void gather_kernel(const float* __restrict__ centers,
                                                     float* __restrict__ out) {
    __shared__ int   idx_s[32][33];
    __shared__ float cs[3][32];

    int b  = blockIdx.y;
    int m0 = blockIdx.x * 32;
    int tid = threadIdx.x;

    for (int t = tid; t < 32 * 32; t += 256) {
        int ml = t >> 5, k = t & 31;
        idx_s[ml][k] = g_idx[((size_t)(b * MCTR + m0 + ml)) * KNB + k];
    }
    if (tid < 96) {
        int coord = tid / 32, ml = tid - coord * 32;
        cs[coord][ml] = centers[(size_t)b * 3 * MCTR + coord * MCTR + m0 + ml];
    }
    __syncthreads();

    int w = tid >> 5, lane = tid & 31;
    const float4* __restrict__ pts = g_pts4 + (size_t)b * NPTS;
    float cx = cs[0][lane], cy = cs[1][lane], cz = cs[2][lane];

    float* ob = out + (size_t)b * (CH * KNB) * MCTR + m0 + lane;

    // prefetch indices, then 4 independent gathered loads (MLP=4)
    int ns[4];
    #pragma unroll
    for (int j = 0; j < 4; j++) ns[j] = idx_s[lane][w + j * 8];
    float4 p[4];
    #pragma unroll
    for (int j = 0; j < 4; j++) p[j] = __ldg(&pts[ns[j]]);

    #pragma unroll
    for (int j = 0; j < 4; j++) {
        int k = w + j * 8;
        float* o = ob + (size_t)k * MCTR;
        o[(size_t)0 * KNB * MCTR] = p[j].x;
        o[(size_t)1 * KNB * MCTR] = p[j].y;
        o[(size_t)2 * KNB * MCTR] = p[j].z;
        o[(size_t)3 * KNB * MCTR] = __fsub_rn(p[j].x, cx);
        o[(size_t)4 * KNB * MCTR] = __fsub_rn(p[j].y, cy);
        o[(size_t)5 * KNB * MCTR] = __fsub_rn(p[j].z, cz);
    }
}

// ---------------------------------------------------------------------------
extern "C" void kernel_launch(void* const* d_in, const int* in_sizes, int n_in,
                              void* d_out, int out_size) {
    const float* pts = (const float*)d_in[0];
    const float* ctr = (const float*)d_in[1];
    if (n_in >= 2 && in_sizes[0] < in_sizes[1]) {
        const float* t = pts; pts = ctr; ctr = t;
    }
    float* out = (float*)d_out;

    build_kernel<<<BATCH, 1024>>>(pts);
    query_kernel<<<(BATCH * MCTR) / 8, 256>>>(ctr);
    dim3 ggrid(MCTR / 32, BATCH);
    gather_kernel<<<ggrid, 256>>>(ctr, out);
}

// round 6
// speedup vs baseline: 1.2885x; 1.2885x over previous
#include <cuda_runtime.h>
#include <cuda_bf16.h>

#define BATCH 4
#define NPTS  16384
#define MCTR  4096
#define KNB   32
#define R2    0.01f
#define RMARG 0.1005f
#define RM2   (RMARG * RMARG)
#define CH    6
#define NCELL 1000          // 10x10x10 per batch
#define TCELL 4096
#define CAP   128

// Scratch (__device__ globals: allocation-guard-safe, zero-initialized)
__device__ float4 g_pts4 [BATCH * NPTS];     // orig order (x,y,z,p2)
__device__ float4 g_spts4[BATCH * NPTS];     // cell-sorted (x,y,z,bitcast idx)
__device__ int    g_cell [BATCH * NPTS];
__device__ int    g_rank [BATCH * NPTS];
__device__ int    g_cnt  [TCELL];            // zeroed at end of each pipeline pass
__device__ int    g_off  [TCELL + 1];
__device__ int    g_idx  [BATCH * MCTR * KNB];

// ---------------------------------------------------------------------------
// pack + per-cell count; remember each point's arrival rank
// ---------------------------------------------------------------------------
__global__ __launch_bounds__(256) void pack_count_kernel(const float* __restrict__ pts) {
    int t = blockIdx.x * blockDim.x + threadIdx.x;
    if (t >= BATCH * NPTS) return;
    int b = t / NPTS, n = t - b * NPTS;
    const float* p = pts + (size_t)b * 3 * NPTS;
    float x = p[n], y = p[NPTS + n], z = p[2 * NPTS + n];
    float p2 = __fmaf_rn(z, z, __fmaf_rn(y, y, __fmul_rn(x, x)));
    g_pts4[t] = make_float4(x, y, z, p2);
    int ci = min(9, max(0, (int)(x * 10.0f)));
    int cj = min(9, max(0, (int)(y * 10.0f)));
    int ck = min(9, max(0, (int)(z * 10.0f)));
    int gc = b * NCELL + (ci * 10 + cj) * 10 + ck;
    g_cell[t] = gc;
    g_rank[t] = atomicAdd(&g_cnt[gc], 1);
}

// ---------------------------------------------------------------------------
// exclusive scan over 4096 cell counts — single block, warp-shuffle 2-level
// ---------------------------------------------------------------------------
__global__ __launch_bounds__(1024) void scan_kernel() {
    __shared__ int wsum[32];
    int tid  = threadIdx.x;
    int lane = tid & 31, wid = tid >> 5;

    int i0 = tid * 4;
    int v0 = g_cnt[i0], v1 = g_cnt[i0 + 1], v2 = g_cnt[i0 + 2], v3 = g_cnt[i0 + 3];
    int local = v0 + v1 + v2 + v3;

    // warp inclusive scan of local
    int inc = local;
    #pragma unroll
    for (int d = 1; d < 32; d <<= 1) {
        int t = __shfl_up_sync(0xffffffffu, inc, d);
        if (lane >= d) inc += t;
    }
    if (lane == 31) wsum[wid] = inc;
    __syncthreads();

    // warp 0 scans the 32 warp totals (exclusive)
    if (wid == 0) {
        int w = wsum[lane];
        int winc = w;
        #pragma unroll
        for (int d = 1; d < 32; d <<= 1) {
            int t = __shfl_up_sync(0xffffffffu, winc, d);
            if (lane >= d) winc += t;
        }
        wsum[lane] = winc - w;   // exclusive
    }
    __syncthreads();

    int excl = wsum[wid] + inc - local;   // exclusive prefix for this thread's 4 slots
    g_off[i0]     = excl;
    g_off[i0 + 1] = excl + v0;
    g_off[i0 + 2] = excl + v0 + v1;
    g_off[i0 + 3] = excl + v0 + v1 + v2;
    if (tid == 1023) g_off[TCELL] = excl + local;
}

// ---------------------------------------------------------------------------
// atomic-free scatter; also re-zeroes g_cnt for the next pipeline pass
// ---------------------------------------------------------------------------
__global__ __launch_bounds__(256) void scatter_kernel() {
    int t = blockIdx.x * blockDim.x + threadIdx.x;
    if (t < TCELL) g_cnt[t] = 0;           // g_cnt dead after scan; reset for next replay
    if (t >= BATCH * NPTS) return;
    int n = t % NPTS;
    int pos = g_off[g_cell[t]] + g_rank[t];
    float4 p = g_pts4[t];
    g_spts4[pos] = make_float4(p.x, p.y, p.z, __int_as_float(n));
}

// ---------------------------------------------------------------------------
// warp-per-center query: merged z-spans, xy-column prune, register bitonic sort
// ---------------------------------------------------------------------------
__global__ __launch_bounds__(256) void query_kernel(const float* __restrict__ centers) {
    __shared__ int lists[8][CAP];
    int gw   = (blockIdx.x * blockDim.x + threadIdx.x) >> 5;
    int wslt = threadIdx.x >> 5;
    int lane = threadIdx.x & 31;
    int b = gw / MCTR, m = gw - b * MCTR;

    const float* c = centers + (size_t)b * 3 * MCTR;
    float cx = c[m], cy = c[MCTR + m], cz = c[2 * MCTR + m];
    float c2 = __fmaf_rn(cz, cz, __fmaf_rn(cy, cy, __fmul_rn(cx, cx)));

    int i0 = max(0, (int)((cx - RMARG) * 10.0f)), i1 = min(9, (int)((cx + RMARG) * 10.0f));
    int j0 = max(0, (int)((cy - RMARG) * 10.0f)), j1 = min(9, (int)((cy + RMARG) * 10.0f));
    int k0 = max(0, (int)((cz - RMARG) * 10.0f)), k1 = min(9, (int)((cz + RMARG) * 10.0f));

    int* lst = lists[wslt];
    unsigned below = (1u << lane) - 1u;
    unsigned cnt = 0;

    for (int ci = i0; ci <= i1; ci++) {
        float lox = ci * 0.1f, hix = lox + 0.1f;
        float dxm = fmaxf(fmaxf(lox - cx, cx - hix), 0.0f);
        float dx2 = dxm * dxm;
        for (int cj = j0; cj <= j1; cj++) {
            float loy = cj * 0.1f, hiy = loy + 0.1f;
            float dym = fmaxf(fmaxf(loy - cy, cy - hiy), 0.0f);
            if (__fmaf_rn(dym, dym, dx2) >= RM2) continue;   // column prune

            int cb = b * NCELL + (ci * 10 + cj) * 10;        // z-cells contiguous
            int start = g_off[cb + k0];
            int end   = g_off[cb + k1 + 1];
            for (int pb = start; pb < end; pb += 32) {
                int p = pb + lane;
                bool hit = false; int idxv = 0;
                if (p < end) {
                    float4 q = g_spts4[p];
                    float p2 = __fmaf_rn(q.z, q.z, __fmaf_rn(q.y, q.y, __fmul_rn(q.x, q.x)));
                    float cp = __fmaf_rn(cz, q.z, __fmaf_rn(cy, q.y, __fmul_rn(cx, q.x)));
                    float d2 = __fsub_rn(__fadd_rn(c2, p2), __fmul_rn(2.0f, cp));
                    hit = d2 < R2;
                    idxv = __float_as_int(q.w);
                }
                unsigned msk = __ballot_sync(0xffffffffu, hit);
                unsigned pos = cnt + __popc(msk & below);
                if (hit && pos < CAP) lst[pos] = idxv;
                cnt += __popc(msk);
            }
        }
    }

    int eff = min((int)cnt, CAP);
    for (int t = eff + lane; t < CAP; t += 32) lst[t] = 0x7fffffff;
    __syncwarp();

    // register bitonic sort of 128 (4 regs/lane, i = q*32 + lane)
    int r[4];
    #pragma unroll
    for (int q = 0; q < 4; q++) r[q] = lst[q * 32 + lane];

    #pragma unroll
    for (int k2 = 2; k2 <= CAP; k2 <<= 1) {
        #pragma unroll
        for (int j = CAP / 2; j > 0; j >>= 1) {
            if (j >= k2) continue;
            if (j >= 32) {
                int jq = j >> 5;
                #pragma unroll
                for (int q = 0; q < 4; q++) {
                    int qp = q ^ jq;
                    if (qp > q) {
                        bool up = (((q * 32 + lane) & k2) == 0);
                        int a = r[q], bb = r[qp];
                        if ((a > bb) == up) { r[q] = bb; r[qp] = a; }
                    }
                }
            } else {
                #pragma unroll
                for (int q = 0; q < 4; q++) {
                    int i = q * 32 + lane;
                    bool up = ((i & k2) == 0);
                    int part = __shfl_xor_sync(0xffffffffu, r[q], j);
                    bool takeMin = (((lane & j) == 0) == up);
                    r[q] = takeMin ? min(r[q], part) : max(r[q], part);
                }
            }
        }
    }

    g_idx[(size_t)gw * KNB + lane] = (lane < eff) ? r[0] : 0;
}

// ---------------------------------------------------------------------------
// tiled gather: 32 centers/block, MLP-4 random loads, coalesced writes along m
// ---------------------------------------------------------------------------
__global__ __launch_bounds__(256) void gather_kernel(const float* __restrict__ centers,
                                                     float* __restrict__ out) {
    __shared__ int   idx_s[32][33];
    __shared__ float cs[3][32];

    int b  = blockIdx.y;
    int m0 = blockIdx.x * 32;
    int tid = threadIdx.x;

    for (int t = tid; t < 32 * 32; t += 256) {
        int ml = t >> 5, k = t & 31;
        idx_s[ml][k] = g_idx[((size_t)(b * MCTR + m0 + ml)) * KNB + k];
    }
    if (tid < 96) {
        int coord = tid / 32, ml = tid - coord * 32;
        cs[coord][ml] = centers[(size_t)b * 3 * MCTR + coord * MCTR + m0 + ml];
    }
    __syncthreads();

    int w = tid >> 5, lane = tid & 31;
    const float4* __restrict__ pts = g_pts4 + (size_t)b * NPTS;
    float cx = cs[0][lane], cy = cs[1][lane], cz = cs[2][lane];

    float* ob = out + (size_t)b * (CH * KNB) * MCTR + m0 + lane;

    // prefetch indices, then 4 independent gathered loads (MLP=4)
    int ns[4];
    #pragma unroll
    for (int j = 0; j < 4; j++) ns[j] = idx_s[lane][w + j * 8];
    float4 p[4];
    #pragma unroll
    for (int j = 0; j < 4; j++) p[j] = __ldg(&pts[ns[j]]);

    #pragma unroll
    for (int j = 0; j < 4; j++) {
        int k = w + j * 8;
        float* o = ob + (size_t)k * MCTR;
        o[(size_t)0 * KNB * MCTR] = p[j].x;
        o[(size_t)1 * KNB * MCTR] = p[j].y;
        o[(size_t)2 * KNB * MCTR] = p[j].z;
        o[(size_t)3 * KNB * MCTR] = __fsub_rn(p[j].x, cx);
        o[(size_t)4 * KNB * MCTR] = __fsub_rn(p[j].y, cy);
        o[(size_t)5 * KNB * MCTR] = __fsub_rn(p[j].z, cz);
    }
}

// ---------------------------------------------------------------------------
extern "C" void kernel_launch(void* const* d_in, const int* in_sizes, int n_in,
                              void* d_out, int out_size) {
    const float* pts = (const float*)d_in[0];
    const float* ctr = (const float*)d_in[1];
    if (n_in >= 2 && in_sizes[0] < in_sizes[1]) {
        const float* t = pts; pts = ctr; ctr = t;
    }
    float* out = (float*)d_out;

    pack_count_kernel<<<(BATCH * NPTS) / 256, 256>>>(pts);
    scan_kernel<<<1, 1024>>>();
    scatter_kernel<<<(BATCH * NPTS) / 256, 256>>>();
    query_kernel<<<(BATCH * MCTR) / 8, 256>>>(ctr);
    dim3 ggrid(MCTR / 32, BATCH);
    gather_kernel<<<ggrid, 256>>>(ctr, out);
}